// round 9
// baseline (speedup 1.0000x reference)
#include <cuda_runtime.h>
#include <cstdint>
#include <math.h>

#define HH 96
#define WW 96
#define HW 9216
typedef unsigned long long ull;

// device scratch (no allocations allowed)
__device__ float g_mask[4*9*HW];                  // sigmoid(mask conv)
__device__ float g_wt[9*64*64];                   // transposed weight [kt][c][o]
__device__ __align__(128) float g_xt[4*HW*64];    // x in NHWC: [b][h][w][c]

#define FMA2(a,b,c) asm("fma.rn.f32x2 %0, %1, %2, %0;" : "+l"(a) : "l"(b), "l"(c))
__device__ __forceinline__ ull dup2(float w) {
    unsigned int u = __float_as_uint(w); ull r;
    asm("mov.b64 %0, {%1, %1};" : "=l"(r) : "r"(u)); return r;
}
__device__ __forceinline__ ull pack2(float lo, float hi_) {
    ull r; asm("mov.b64 %0, {%1, %2};" : "=l"(r) : "f"(lo), "f"(hi_)); return r;
}

// ---------------- kernel 0: NCHW -> NHWC transpose ----------------
__global__ __launch_bounds__(256) void k_nhwc(const float* __restrict__ x) {
    __shared__ float tile[64][65];
    int t = threadIdx.x;
    int b = blockIdx.y;
    int px0 = blockIdx.x*64;
    int px = t & 63, cg = t >> 6;
    const float* xb = x + (size_t)b*64*HW + px0 + px;
    #pragma unroll
    for (int i = 0; i < 16; i++) {
        int c = cg*16 + i;
        tile[px][c] = xb[(size_t)c*HW];
    }
    __syncthreads();
    float* ob = g_xt + (size_t)b*HW*64 + (size_t)px0*64;
    #pragma unroll
    for (int jj = 0; jj < 4; jj++) {
        int id = jj*256 + t;
        int p = id >> 4, c16 = id & 15;
        float4 v = make_float4(tile[p][c16*4], tile[p][c16*4+1],
                               tile[p][c16*4+2], tile[p][c16*4+3]);
        *(float4*)(ob + p*64 + c16*4) = v;
    }
}

// ---------------- kernel 1: mask conv (px-paired f32x2) + weight transpose ----------------
__global__ __launch_bounds__(256) void k_mask(const float* __restrict__ x,
                                              const float* __restrict__ mw,
                                              const float* __restrict__ mb,
                                              const float* __restrict__ wgt) {
    __shared__ ull sdw[64*90];      // dup'd mask weights [c][k*10+t]
    __shared__ float sbias[9];
    int tid = threadIdx.x;
    int t0 = blockIdx.x*256 + tid;              // 0..18431

    // merged weight transpose for the main GEMM: 2 elements per thread
    #pragma unroll
    for (int u = 0; u < 2; u++) {
        int e = t0 + u*18432;
        int o = e & 63, c = (e >> 6) & 63, kt = e >> 12;
        g_wt[e] = wgt[o*576 + c*9 + kt];
    }

    for (int i = tid; i < 5184; i += 256) {
        int k = i / 576; int r = i % 576; int c = r / 9; int tt = r % 9;
        sdw[c*90 + k*10 + tt] = dup2(mw[i]);
    }
    if (tid < 9) sbias[tid] = mb[tid];
    __syncthreads();

    int b = t0 / (HW/2);
    int r = t0 % (HW/2);
    int h = r / (WW/2);
    int w = (r % (WW/2)) * 2;                   // pixel pair (w, w+1)

    ull acc[9];
    #pragma unroll
    for (int k = 0; k < 9; k++) acc[k] = dup2(sbias[k]);

    const float* xb = x + (size_t)b*64*HW;
    for (int c = 0; c < 64; c++) {
        float v[3][4];
        #pragma unroll
        for (int i = 0; i < 3; i++)
          #pragma unroll
          for (int j = 0; j < 4; j++) {
            int yy = h + i - 1, xx = w + j - 1;
            bool ok = (yy >= 0) && (yy < HH) && (xx >= 0) && (xx < WW);
            v[i][j] = ok ? __ldg(xb + c*HW + yy*WW + xx) : 0.f;
          }
        ull s[9];
        #pragma unroll
        for (int i = 0; i < 3; i++)
          #pragma unroll
          for (int j = 0; j < 3; j++)
            s[i*3+j] = pack2(v[i][j], v[i][j+1]);
        const ull* wr = sdw + c*90;
        #pragma unroll
        for (int k = 0; k < 9; k++)
          #pragma unroll
          for (int tt = 0; tt < 9; tt++)
            FMA2(acc[k], wr[k*10 + tt], s[tt]);
    }
    #pragma unroll
    for (int k = 0; k < 9; k++) {
        float2 f = *(float2*)&acc[k];
        f.x = 1.f/(1.f + __expf(-f.x));
        f.y = 1.f/(1.f + __expf(-f.y));
        *(float2*)(g_mask + ((size_t)(b*9 + k)*HH + h)*WW + w) = f;
    }
}

// ---------------- kernel 2: NHWC gather + double-buffered register GEMM ----------------
#define S_SS 132
#define S_WT 72
#define SS_FL (64*S_SS)     // 8448
#define WT_FL (64*S_WT)     // 4608

__global__ __launch_bounds__(256, 2) void k_deform(const float* __restrict__ offset,
                                                   float* __restrict__ out) {
    extern __shared__ float sm[];
    float* ssamA = sm;
    float* ssamB = sm + SS_FL;
    float* swtA  = sm + 2*SS_FL;
    float* swtB  = swtA + WT_FL;
    float* spar  = swtA + 2*WT_FL;       // [128 px][8]

    int tid  = threadIdx.x;
    int wid  = tid >> 5, lane = tid & 31;
    int qh   = lane & 15;
    int hi   = lane >> 4;                // 0 = left x-corner, 1 = right
    int b    = blockIdx.y;
    int pix0 = blockIdx.x * 128;
    int og   = tid & 7, pg = tid >> 3;   // 8 o-groups x 32 px-groups(4 px)

    int ppx   = wid*16 + qh;             // param pixel (lanes hi==0 active)
    int mypix = pix0 + ppx;
    int ph = mypix / WW, pw = mypix % WW;
    const float* xb = g_xt + (size_t)b*HW*64;
    float* mypar = spar + ppx*8;

    ull acc[8][2];
    #pragma unroll
    for (int o = 0; o < 8; o++) { acc[o][0] = 0ULL; acc[o][1] = 0ULL; }

    // ---- param compute for tap kt (one lane per pixel, lanes hi==0) ----
    auto params = [&](int kt) {
        if (hi == 0) {
            float oy = offset[(size_t)(b*18 + 2*kt    )*HW + mypix];
            float ox = offset[(size_t)(b*18 + 2*kt + 1)*HW + mypix];
            float mk = g_mask[(size_t)(b*9 + kt)*HW + mypix];
            int ky = kt/3, kx = kt - ky*3;
            float py  = (float)(ph - 1 + ky) + oy;
            float pxf = (float)(pw - 1 + kx) + ox;
            float y0f = floorf(py), x0f = floorf(pxf);
            int y0 = (int)y0f, x0 = (int)x0f;
            float wy = py - y0f, wx = pxf - x0f;
            float w11 = mk*wy*wx;
            float w10 = mk*wy - w11;
            float w01 = mk*wx - w11;
            float w00 = mk - mk*wy - mk*wx + w11;
            if (!((y0 >=  0) & (y0 < HH)   & (x0 >=  0) & (x0 < WW)))   w00 = 0.f;
            if (!((y0 >=  0) & (y0 < HH)   & (x0 >= -1) & (x0 < WW-1))) w01 = 0.f;
            if (!((y0 >= -1) & (y0 < HH-1) & (x0 >=  0) & (x0 < WW)))   w10 = 0.f;
            if (!((y0 >= -1) & (y0 < HH-1) & (x0 >= -1) & (x0 < WW-1))) w11 = 0.f;
            int yc0 = min(max(y0,   0), HH-1), yc1 = min(max(y0+1, 0), HH-1);
            int xc0 = min(max(x0,   0), WW-1), xc1 = min(max(x0+1, 0), WW-1);
            ((float4*)mypar)[0] = make_float4(w00, w01, w10, w11);
            ((float4*)mypar)[1] = make_float4(
                __int_as_float((yc0*WW + xc0)*64), __int_as_float((yc0*WW + xc1)*64),
                __int_as_float((yc1*WW + xc0)*64), __int_as_float((yc1*WW + xc1)*64));
        }
    };

    // stage weights: row layout [og*4+u]=o(og*8+u), [32+og*4+u]=o(og*8+4+u)
    auto stage_w = [&](int kt, float* dst) {
        const float4* wsrc = (const float4*)(g_wt + kt*4096);
        #pragma unroll
        for (int i = 0; i < 4; i++) {
            int idx = i*256 + tid;
            int c = idx >> 4, o4 = idx & 15;
            int slot = (o4 & 1)*32 + (o4 >> 1)*4;
            *(float4*)(dst + c*S_WT + slot) = wsrc[idx];
        }
    };

    float4 T[4], Bv[4];
    auto ldg_round = [&](int r) {
        int px0r = wid*16 + r*4;
        #pragma unroll
        for (int j = 0; j < 4; j++) {
            float4 pa = ((const float4*)(spar + (px0r + j)*8))[1];
            int aT = __float_as_int(hi ? pa.y : pa.x) + qh*4;
            int aB = __float_as_int(hi ? pa.w : pa.z) + qh*4;
            T[j]  = *(const float4*)(xb + aT);
            Bv[j] = *(const float4*)(xb + aB);
        }
    };

    auto combine_sts = [&](int r, float* ns) {
        int px0r = wid*16 + r*4;
        float4 v[4];
        #pragma unroll
        for (int j = 0; j < 4; j++) {
            float4 wv = ((const float4*)(spar + (px0r + j)*8))[0];
            float wt_ = hi ? wv.y : wv.x;
            float wb_ = hi ? wv.w : wv.z;
            float sx = T[j].x*wt_ + Bv[j].x*wb_;
            float sy = T[j].y*wt_ + Bv[j].y*wb_;
            float sz = T[j].z*wt_ + Bv[j].z*wb_;
            float sw = T[j].w*wt_ + Bv[j].w*wb_;
            v[j].x = sx + __shfl_xor_sync(0xffffffffu, sx, 16);
            v[j].y = sy + __shfl_xor_sync(0xffffffffu, sy, 16);
            v[j].z = sz + __shfl_xor_sync(0xffffffffu, sz, 16);
            v[j].w = sw + __shfl_xor_sync(0xffffffffu, sw, 16);
        }
        int p4   = wid*4 + r;
        int slot = (p4 ^ (qh & 7)) * 4;
        if (hi == 0) {
            *(float4*)(ns + (4*qh + 0)*S_SS + slot) = make_float4(v[0].x, v[1].x, v[2].x, v[3].x);
            *(float4*)(ns + (4*qh + 1)*S_SS + slot) = make_float4(v[0].y, v[1].y, v[2].y, v[3].y);
        } else {
            *(float4*)(ns + (4*qh + 2)*S_SS + slot) = make_float4(v[0].z, v[1].z, v[2].z, v[3].z);
            *(float4*)(ns + (4*qh + 3)*S_SS + slot) = make_float4(v[0].w, v[1].w, v[2].w, v[3].w);
        }
    };

    // ---- prologue: tap 0 ----
    params(0); __syncwarp();
    stage_w(0, swtA);
    #pragma unroll 1
    for (int r = 0; r < 4; r++) { ldg_round(r); combine_sts(r, ssamA); }
    __syncthreads();

    // ---- main: GEMM(kt) overlapped with gather(kt+1) ----
    #pragma unroll 1
    for (int kt = 0; kt < 9; kt++) {
        float* cs = (kt & 1) ? ssamB : ssamA;
        float* cw = (kt & 1) ? swtB  : swtA;
        float* ns = (kt & 1) ? ssamA : ssamB;
        float* nw = (kt & 1) ? swtA  : swtB;
        bool more = (kt < 8);
        if (more) {
            params(kt + 1); __syncwarp();
            stage_w(kt + 1, nw);
        }
        #pragma unroll 1
        for (int r = 0; r < 4; r++) {
            if (more) ldg_round(r);
            #pragma unroll 4
            for (int cc = 0; cc < 16; cc++) {
                int c = r*16 + cc;
                const float* wrow = cw + c*S_WT;
                float4 wa  = *(const float4*)(wrow + og*4);
                float4 wb2 = *(const float4*)(wrow + 32 + og*4);
                int xr = (c >> 2) & 7;
                float4 sv = ((const float4*)(cs + c*S_SS))[pg ^ xr];
                ull s0 = ((ull*)&sv)[0], s1 = ((ull*)&sv)[1];
                float wf[8] = {wa.x, wa.y, wa.z, wa.w, wb2.x, wb2.y, wb2.z, wb2.w};
                #pragma unroll
                for (int o = 0; o < 8; o++) {
                    ull wd = dup2(wf[o]);
                    FMA2(acc[o][0], wd, s0);
                    FMA2(acc[o][1], wd, s1);
                }
            }
            if (more) combine_sts(r, ns);
        }
        __syncthreads();
    }

    // ---- epilogue: packed stores (f32x2 lanes = adjacent pixels) ----
    float* ob = out + (size_t)b*64*HW + pix0 + pg*4;
    #pragma unroll
    for (int i = 0; i < 8; i++) {
        // outputs og*8+i (halves 0..3 / 4..7 map o = og*8 + i directly)
        int o = og*8 + i;
        float* op = ob + (size_t)o*HW;
        *(ull*)(op)     = acc[i][0];
        *(ull*)(op + 2) = acc[i][1];
    }
}

// ---------------- launch ----------------
extern "C" void kernel_launch(void* const* d_in, const int* in_sizes, int n_in,
                              void* d_out, int out_size) {
    const float* x      = (const float*)d_in[0];
    const float* offset = (const float*)d_in[1];
    const float* weight = (const float*)d_in[2];
    const float* mw     = (const float*)d_in[3];
    const float* mb     = (const float*)d_in[4];
    float* out = (float*)d_out;
    (void)in_sizes; (void)n_in; (void)out_size;

    const int SMEM = (2*SS_FL + 2*WT_FL + 128*8) * 4;   // 108544 B
    cudaFuncSetAttribute(k_deform, cudaFuncAttributeMaxDynamicSharedMemorySize, SMEM);

    dim3 tg(HW/64, 4);
    k_nhwc<<<tg, 256>>>(x);
    k_mask<<<72, 256>>>(x, mw, mb, weight);
    dim3 grid(HW/128, 4);                // (72, 4)
    k_deform<<<grid, 256, SMEM>>>(offset, out);
}

// round 10
// speedup vs baseline: 1.3855x; 1.3855x over previous
#include <cuda_runtime.h>
#include <cstdint>
#include <math.h>

#define HH 96
#define WW 96
#define HW 9216
typedef unsigned long long ull;

// device scratch (no allocations allowed)
__device__ float g_mask[4*9*HW];                    // sigmoid(mask conv)
__device__ __align__(16) float g_wtB[9*8*8*64];     // frag-ordered tf32 weights [kt][ks][ni][lane*2+h]
__device__ __align__(128) float g_xt[4*HW*64];      // x in NHWC: [b][h][w][c]

#define FMA2(a,b,c) asm("fma.rn.f32x2 %0, %1, %2, %0;" : "+l"(a) : "l"(b), "l"(c))
__device__ __forceinline__ ull dup2(float w) {
    unsigned int u = __float_as_uint(w); ull r;
    asm("mov.b64 %0, {%1, %1};" : "=l"(r) : "r"(u)); return r;
}
__device__ __forceinline__ ull pack2(float lo, float hi_) {
    ull r; asm("mov.b64 %0, {%1, %2};" : "=l"(r) : "f"(lo), "f"(hi_)); return r;
}
__device__ __forceinline__ float cvt_tf32(float v) {
    float r; asm("cvt.rna.tf32.f32 %0, %1;" : "=f"(r) : "f"(v)); return r;
}
__device__ __forceinline__ void mma8(float* d, const uint32_t* a, uint32_t b0, uint32_t b1) {
    asm volatile("mma.sync.aligned.m16n8k8.row.col.f32.tf32.tf32.f32 "
        "{%0,%1,%2,%3}, {%4,%5,%6,%7}, {%8,%9}, {%0,%1,%2,%3};"
        : "+f"(d[0]), "+f"(d[1]), "+f"(d[2]), "+f"(d[3])
        : "r"(a[0]), "r"(a[1]), "r"(a[2]), "r"(a[3]), "r"(b0), "r"(b1));
}

// ---------------- kernel 0: NCHW -> NHWC transpose ----------------
__global__ __launch_bounds__(256) void k_nhwc(const float* __restrict__ x) {
    __shared__ float tile[64][65];
    int t = threadIdx.x;
    int b = blockIdx.y;
    int px0 = blockIdx.x*64;
    int px = t & 63, cg = t >> 6;
    const float* xb = x + (size_t)b*64*HW + px0 + px;
    #pragma unroll
    for (int i = 0; i < 16; i++) {
        int c = cg*16 + i;
        tile[px][c] = xb[(size_t)c*HW];
    }
    __syncthreads();
    float* ob = g_xt + (size_t)b*HW*64 + (size_t)px0*64;
    #pragma unroll
    for (int jj = 0; jj < 4; jj++) {
        int id = jj*256 + t;
        int p = id >> 4, c16 = id & 15;
        float4 v = make_float4(tile[p][c16*4], tile[p][c16*4+1],
                               tile[p][c16*4+2], tile[p][c16*4+3]);
        *(float4*)(ob + p*64 + c16*4) = v;
    }
}

// ---------------- kernel 1: mask conv (px-paired f32x2) + frag-weight prep ----------------
__global__ __launch_bounds__(256) void k_mask(const float* __restrict__ x,
                                              const float* __restrict__ mw,
                                              const float* __restrict__ mb,
                                              const float* __restrict__ wgt) {
    __shared__ ull sdw[64*90];
    __shared__ float sbias[9];
    int tid = threadIdx.x;
    int t0 = blockIdx.x*256 + tid;              // 0..18431

    // frag-ordered tf32 weight prep: b0 = B[k=l%4][n=l/4], b1 = k+4
    #pragma unroll
    for (int u = 0; u < 2; u++) {
        int e = t0 + u*18432;
        int j  = e & 63;
        int ni = (e >> 6) & 7;
        int ks = (e >> 9) & 7;
        int kt = e >> 12;
        int l  = j >> 1, h = j & 1;
        int c  = ks*8 + (l & 3) + h*4;
        int o  = ni*8 + (l >> 2);
        g_wtB[e] = cvt_tf32(wgt[o*576 + c*9 + kt]);
    }

    for (int i = tid; i < 5184; i += 256) {
        int k = i / 576; int r = i % 576; int c = r / 9; int tt = r % 9;
        sdw[c*90 + k*10 + tt] = dup2(mw[i]);
    }
    if (tid < 9) sbias[tid] = mb[tid];
    __syncthreads();

    int b = t0 / (HW/2);
    int r = t0 % (HW/2);
    int h = r / (WW/2);
    int w = (r % (WW/2)) * 2;

    ull acc[9];
    #pragma unroll
    for (int k = 0; k < 9; k++) acc[k] = dup2(sbias[k]);

    const float* xb = x + (size_t)b*64*HW;
    for (int c = 0; c < 64; c++) {
        float v[3][4];
        #pragma unroll
        for (int i = 0; i < 3; i++)
          #pragma unroll
          for (int j = 0; j < 4; j++) {
            int yy = h + i - 1, xx = w + j - 1;
            bool ok = (yy >= 0) && (yy < HH) && (xx >= 0) && (xx < WW);
            v[i][j] = ok ? __ldg(xb + c*HW + yy*WW + xx) : 0.f;
          }
        ull s[9];
        #pragma unroll
        for (int i = 0; i < 3; i++)
          #pragma unroll
          for (int j = 0; j < 3; j++)
            s[i*3+j] = pack2(v[i][j], v[i][j+1]);
        const ull* wr = sdw + c*90;
        #pragma unroll
        for (int k = 0; k < 9; k++)
          #pragma unroll
          for (int tt = 0; tt < 9; tt++)
            FMA2(acc[k], wr[k*10 + tt], s[tt]);
    }
    #pragma unroll
    for (int k = 0; k < 9; k++) {
        float2 f = *(float2*)&acc[k];
        f.x = 1.f/(1.f + __expf(-f.x));
        f.y = 1.f/(1.f + __expf(-f.y));
        *(float2*)(g_mask + ((size_t)(b*9 + k)*HH + h)*WW + w) = f;
    }
}

// ---------------- kernel 2: warp-independent NHWC gather + tf32 mma.sync GEMM ----------------
#define S_SS 132
#define SS_FL (64*S_SS)     // 8448

__global__ __launch_bounds__(128, 3) void k_deform(const float* __restrict__ offset,
                                                   float* __restrict__ out) {
    extern __shared__ float sm[];
    float* ssamA = sm;              // [64 c][132]
    float* ssamB = sm + SS_FL;
    float* spar  = sm + 2*SS_FL;    // [128 px][8]

    int tid  = threadIdx.x;
    int wid  = tid >> 5, lane = tid & 31;
    int qh   = lane & 15;
    int hi   = lane >> 4;
    int l4   = lane >> 2, lm = lane & 3;
    int b    = blockIdx.y;
    int pix0 = blockIdx.x * 128;
    int mb0  = wid * 32;             // this warp's pixel base (local)

    int gpx   = wid*32 + lane;
    int mypix = pix0 + gpx;
    int ph = mypix / WW, pw = mypix % WW;
    const float* xb = g_xt + (size_t)b*HW*64;
    float* mypar = spar + gpx*8;

    float d[64];                     // [ni*2+mi][4]
    #pragma unroll
    for (int i = 0; i < 64; i++) d[i] = 0.f;

    auto params = [&](int kt) {
        float oy = offset[(size_t)(b*18 + 2*kt    )*HW + mypix];
        float ox = offset[(size_t)(b*18 + 2*kt + 1)*HW + mypix];
        float mk = g_mask[(size_t)(b*9 + kt)*HW + mypix];
        int ky = kt/3, kx = kt - ky*3;
        float py  = (float)(ph - 1 + ky) + oy;
        float pxf = (float)(pw - 1 + kx) + ox;
        float y0f = floorf(py), x0f = floorf(pxf);
        int y0 = (int)y0f, x0 = (int)x0f;
        float wy = py - y0f, wx = pxf - x0f;
        float w11 = mk*wy*wx;
        float w10 = mk*wy - w11;
        float w01 = mk*wx - w11;
        float w00 = mk - mk*wy - mk*wx + w11;
        if (!((y0 >=  0) & (y0 < HH)   & (x0 >=  0) & (x0 < WW)))   w00 = 0.f;
        if (!((y0 >=  0) & (y0 < HH)   & (x0 >= -1) & (x0 < WW-1))) w01 = 0.f;
        if (!((y0 >= -1) & (y0 < HH-1) & (x0 >=  0) & (x0 < WW)))   w10 = 0.f;
        if (!((y0 >= -1) & (y0 < HH-1) & (x0 >= -1) & (x0 < WW-1))) w11 = 0.f;
        int yc0 = min(max(y0,   0), HH-1), yc1 = min(max(y0+1, 0), HH-1);
        int xc0 = min(max(x0,   0), WW-1), xc1 = min(max(x0+1, 0), WW-1);
        ((float4*)mypar)[0] = make_float4(w00, w01, w10, w11);
        ((float4*)mypar)[1] = make_float4(
            __int_as_float((yc0*WW + xc0)*64), __int_as_float((yc0*WW + xc1)*64),
            __int_as_float((yc1*WW + xc0)*64), __int_as_float((yc1*WW + xc1)*64));
    };

    float4 T[4], Bv[4];
    auto ldg_round = [&](int g) {
        int px0r = wid*32 + g*4;
        #pragma unroll
        for (int r = 0; r < 4; r++) {
            float4 pa = ((const float4*)(spar + (px0r + r)*8))[1];
            int aT = __float_as_int(hi ? pa.y : pa.x) + qh*4;
            int aB = __float_as_int(hi ? pa.w : pa.z) + qh*4;
            T[r]  = *(const float4*)(xb + aT);
            Bv[r] = *(const float4*)(xb + aB);
        }
    };

    auto combine_sts = [&](int g, float* ns) {
        int px0r = wid*32 + g*4;
        float4 v[4];
        #pragma unroll
        for (int r = 0; r < 4; r++) {
            float4 wv = ((const float4*)(spar + (px0r + r)*8))[0];
            float wt_ = hi ? wv.y : wv.x;
            float wb_ = hi ? wv.w : wv.z;
            float sx = T[r].x*wt_ + Bv[r].x*wb_;
            float sy = T[r].y*wt_ + Bv[r].y*wb_;
            float sz = T[r].z*wt_ + Bv[r].z*wb_;
            float sw = T[r].w*wt_ + Bv[r].w*wb_;
            v[r].x = cvt_tf32(sx + __shfl_xor_sync(0xffffffffu, sx, 16));
            v[r].y = cvt_tf32(sy + __shfl_xor_sync(0xffffffffu, sy, 16));
            v[r].z = cvt_tf32(sz + __shfl_xor_sync(0xffffffffu, sz, 16));
            v[r].w = cvt_tf32(sw + __shfl_xor_sync(0xffffffffu, sw, 16));
        }
        int p4   = wid*8 + g;
        int slot = (p4 ^ (qh & 7)) * 4;
        if (hi == 0) {
            *(float4*)(ns + (4*qh + 0)*S_SS + slot) = make_float4(v[0].x, v[1].x, v[2].x, v[3].x);
            *(float4*)(ns + (4*qh + 1)*S_SS + slot) = make_float4(v[0].y, v[1].y, v[2].y, v[3].y);
        } else {
            *(float4*)(ns + (4*qh + 2)*S_SS + slot) = make_float4(v[0].z, v[1].z, v[2].z, v[3].z);
            *(float4*)(ns + (4*qh + 3)*S_SS + slot) = make_float4(v[0].w, v[1].w, v[2].w, v[3].w);
        }
    };

    // element (c, px) lives at c*S_SS + ((px>>2)^((c>>2)&7))*4 + (px&3)
    auto lda = [&](const float* buf, int c, int px) -> uint32_t {
        return __float_as_uint(buf[c*S_SS + ((((px>>2) ^ ((c>>2)&7)) << 2) | (px & 3))]);
    };

    // ---- prologue: gather tap 0 (warp-private, no block syncs anywhere) ----
    params(0); __syncwarp();
    #pragma unroll 1
    for (int g = 0; g < 8; g++) { ldg_round(g); combine_sts(g, ssamA); }
    __syncwarp();

    // ---- main: mma(kt) overlapped with gather(kt+1) ----
    #pragma unroll 1
    for (int kt = 0; kt < 9; kt++) {
        const float* cur = (kt & 1) ? ssamB : ssamA;
        float* nxt = (kt & 1) ? ssamA : ssamB;
        bool more = (kt < 8);
        if (more) { params(kt + 1); __syncwarp(); }
        #pragma unroll 1
        for (int r = 0; r < 8; r++) {
            if (more) ldg_round(r);
            int cb = r*8;
            uint32_t a0[4], a1[4];
            a0[0] = lda(cur, cb+lm,   mb0+l4);
            a0[1] = lda(cur, cb+lm,   mb0+l4+8);
            a0[2] = lda(cur, cb+lm+4, mb0+l4);
            a0[3] = lda(cur, cb+lm+4, mb0+l4+8);
            a1[0] = lda(cur, cb+lm,   mb0+16+l4);
            a1[1] = lda(cur, cb+lm,   mb0+24+l4);
            a1[2] = lda(cur, cb+lm+4, mb0+16+l4);
            a1[3] = lda(cur, cb+lm+4, mb0+24+l4);
            const ull* bw = (const ull*)(g_wtB + (kt*8 + r)*512) + lane;
            #pragma unroll
            for (int ni = 0; ni < 8; ni++) {
                ull bp = __ldg(bw + ni*32);
                uint32_t b0 = (uint32_t)bp, b1 = (uint32_t)(bp >> 32);
                mma8(d + (ni*2 + 0)*4, a0, b0, b1);
                mma8(d + (ni*2 + 1)*4, a1, b0, b1);
            }
            if (more) combine_sts(r, nxt);
        }
        __syncwarp();
    }

    // ---- epilogue: D[m=px][n=o] fragment stores ----
    float* ob = out + (size_t)b*64*HW + pix0;
    #pragma unroll
    for (int ni = 0; ni < 8; ni++)
      #pragma unroll
      for (int mi = 0; mi < 2; mi++) {
        int px = mb0 + mi*16 + l4;
        int o  = ni*8 + lm*2;
        const float* dd = d + (ni*2 + mi)*4;
        ob[(size_t)o*HW + px]         = dd[0];
        ob[(size_t)(o+1)*HW + px]     = dd[1];
        ob[(size_t)o*HW + px + 8]     = dd[2];
        ob[(size_t)(o+1)*HW + px + 8] = dd[3];
      }
}

// ---------------- launch ----------------
extern "C" void kernel_launch(void* const* d_in, const int* in_sizes, int n_in,
                              void* d_out, int out_size) {
    const float* x      = (const float*)d_in[0];
    const float* offset = (const float*)d_in[1];
    const float* weight = (const float*)d_in[2];
    const float* mw     = (const float*)d_in[3];
    const float* mb     = (const float*)d_in[4];
    float* out = (float*)d_out;
    (void)in_sizes; (void)n_in; (void)out_size;

    const int SMEM = (2*SS_FL + 128*8) * 4;   // 71680 B -> 3 blocks/SM
    cudaFuncSetAttribute(k_deform, cudaFuncAttributeMaxDynamicSharedMemorySize, SMEM);

    dim3 tg(HW/64, 4);
    k_nhwc<<<tg, 256>>>(x);
    k_mask<<<72, 256>>>(x, mw, mb, weight);
    dim3 grid(HW/128, 4);                // (72, 4)
    k_deform<<<grid, 128, SMEM>>>(offset, out);
}